// round 16
// baseline (speedup 1.0000x reference)
#include <cuda_runtime.h>

#define TILE_W  54          // output cols per block
#define TILE_H  32          // output rows per block
#define VCOLS   64          // input cols = TILE_W + 10
#define VSTR    65          // V row stride in float4 (col 64 = pad; reused for wsum)
#define IMG     512
#define OUTD    502
#define NPLANE  48

#define SMEM_TOTAL (TILE_H * VSTR * 16)     // 33280 = 260*128 -> 7 CTAs/SM

__global__ void ssim_zero_kernel(float* out, int n) {
    int i = threadIdx.x;
    if (i < n) out[i] = 0.0f;
}

__global__ __launch_bounds__(256, 7) void ssim_kernel(const float* __restrict__ img1,
                                                      const float* __restrict__ img2,
                                                      float* __restrict__ out) {
    extern __shared__ char smem_raw[];
    float4 (*V)[VSTR] = (float4 (*)[VSTR])smem_raw;   // vertical 11-sums, 32 rows x 64 cols
    // wsum aliased into the unused pad column: V[w][64].x, w = 0..7 (never touched
    // by phase 1/2, which only access cols 0..63).
    #define WSUM(w) (V[w][64].x)

    const int plane = blockIdx.z;
    const int batch = plane / 3;
    const int ox0 = blockIdx.x * TILE_W;
    const int oy0 = blockIdx.y * TILE_H;

    const float* __restrict__ p1 = img1 + (size_t)plane * IMG * IMG;
    const float* __restrict__ p2 = img2 + (size_t)plane * IMG * IMG;

    const int tid = threadIdx.x;

    // ---- Phase 1: vertical sliding 11-sums straight from GMEM (coalesced).
    //      256 threads: col c = tid&63, chunk = tid>>6 -> V rows chunk*8..chunk*8+7. ----
    {
        const int c  = tid & 63;
        const int r0 = (tid >> 6) * 8;

        // Block-uniform fast path: whole 42-row x 64-col input window in-bounds.
        if (oy0 + TILE_H + 10 <= IMG && ox0 + VCOLS <= IMG) {
            // All row addresses are base + k*IMG with compile-time k -> LDG [R, imm].
            const float* __restrict__ q1 = p1 + (size_t)(oy0 + r0) * IMG + (ox0 + c);
            const float* __restrict__ q2 = p2 + (size_t)(oy0 + r0) * IMG + (ox0 + c);

            float sa = 0.f, sb = 0.f, sp = 0.f, sm = 0.f;
            #pragma unroll
            for (int k = 0; k < 10; k++) {
                const float a = __saturatef(__ldg(q1 + k * IMG));
                const float b = __saturatef(__ldg(q2 + k * IMG));
                const float pq = a + b, mq = a - b;
                sa += a; sb += b; sp += pq * pq; sm += mq * mq;
            }
            #pragma unroll
            for (int j = 0; j < 8; j++) {
                {   // enter row j+10
                    const float a = __saturatef(__ldg(q1 + (j + 10) * IMG));
                    const float b = __saturatef(__ldg(q2 + (j + 10) * IMG));
                    const float pq = a + b, mq = a - b;
                    sa += a; sb += b; sp += pq * pq; sm += mq * mq;
                }
                V[r0 + j][c] = make_float4(sa, sb, sp, sm);
                {   // exit row j (identical address to prologue load -> CSE/L1 hit)
                    const float a = __saturatef(__ldg(q1 + j * IMG));
                    const float b = __saturatef(__ldg(q2 + j * IMG));
                    const float pq = a + b, mq = a - b;
                    sa -= a; sb -= b; sp -= pq * pq; sm -= mq * mq;
                }
            }
        } else {
            // Boundary tiles: clamped coordinates (clamped lanes/rows only feed
            // guarded-out outputs).
            const int gx = min(ox0 + c, IMG - 1);
            const float* __restrict__ q1 = p1 + gx;
            const float* __restrict__ q2 = p2 + gx;

            float sa = 0.f, sb = 0.f, sp = 0.f, sm = 0.f;
            #pragma unroll
            for (int k = 0; k < 10; k++) {
                const int gy = min(oy0 + r0 + k, IMG - 1);
                const float a = __saturatef(__ldg(q1 + gy * IMG));
                const float b = __saturatef(__ldg(q2 + gy * IMG));
                const float pq = a + b, mq = a - b;
                sa += a; sb += b; sp += pq * pq; sm += mq * mq;
            }
            #pragma unroll
            for (int j = 0; j < 8; j++) {
                {
                    const int gy = min(oy0 + r0 + j + 10, IMG - 1);
                    const float a = __saturatef(__ldg(q1 + gy * IMG));
                    const float b = __saturatef(__ldg(q2 + gy * IMG));
                    const float pq = a + b, mq = a - b;
                    sa += a; sb += b; sp += pq * pq; sm += mq * mq;
                }
                V[r0 + j][c] = make_float4(sa, sb, sp, sm);
                {
                    const int gy = min(oy0 + r0 + j, IMG - 1);
                    const float a = __saturatef(__ldg(q1 + gy * IMG));
                    const float b = __saturatef(__ldg(q2 + gy * IMG));
                    const float pq = a + b, mq = a - b;
                    sa -= a; sb -= b; sp -= pq * pq; sm -= mq * mq;
                }
            }
        }
    }
    __syncthreads();

    // ---- Phase 2: horizontal sliding 11-sums of V + SSIM.
    //      256 threads: row = tid&31, span = tid>>5 (8 spans of 7 outputs).
    //      Max V col touched: s0+j+10 <= 49+6+10 = 63 (col 64 stays free for wsum). ----
    const float C1 = 1e-4f;
    const float C2 = 9e-4f;
    const float inv121 = 1.0f / 121.0f;
    const float inv242 = 1.0f / 242.0f;
    const float inv484 = 1.0f / 484.0f;

    float acc = 0.0f;
    {
        const int row = tid & 31;
        const int s0  = (tid >> 5) * 7;
        const bool rowok = (oy0 + row) < OUTD;

        float sa = 0.f, sb = 0.f, sp = 0.f, sm = 0.f;
        #pragma unroll
        for (int k = 0; k < 10; k++) {
            const float4 h = V[row][s0 + k];
            sa += h.x; sb += h.y; sp += h.z; sm += h.w;
        }
        #pragma unroll
        for (int j = 0; j < 7; j++) {
            if (s0 + j < TILE_W) {          // last span covers only 5 outputs
                {
                    const float4 h = V[row][s0 + j + 10];
                    sa += h.x; sb += h.y; sp += h.z; sm += h.w;
                }
                const int ox = ox0 + s0 + j;
                if (rowok && ox < OUTD) {
                    const float mu1  = sa * inv121;
                    const float mu2  = sb * inv121;
                    const float musq = mu1 * mu1 + mu2 * mu2;
                    const float mu12 = mu1 * mu2;
                    const float e_sq = (sp + sm) * inv242;   // E[a^2 + b^2]
                    const float e_ab = (sp - sm) * inv484;   // E[ab]
                    const float vsum = e_sq - musq;          // v1 + v2
                    const float v12  = e_ab - mu12;
                    const float num = (2.0f * mu12 + C1) * (2.0f * v12 + C2);
                    const float den = (musq + C1) * (vsum + C2);
                    acc += __fdividef(num, den);
                }
                {
                    const float4 h = V[row][s0 + j];
                    sa -= h.x; sb -= h.y; sp -= h.z; sm -= h.w;
                }
            }
        }
    }

    // ---- Block reduction (wsum lives in V pad column; no extra smem) ----
    #pragma unroll
    for (int o = 16; o > 0; o >>= 1)
        acc += __shfl_down_sync(0xffffffffu, acc, o);
    if ((tid & 31) == 0) WSUM(tid >> 5) = acc;
    __syncthreads();
    if (tid == 0) {
        float t = 0.0f;
        #pragma unroll
        for (int i = 0; i < 8; i++) t += WSUM(i);
        const float scale = 1.0f / (3.0f * (float)OUTD * (float)OUTD);
        atomicAdd(out + batch, t * scale);
    }
}

extern "C" void kernel_launch(void* const* d_in, const int* in_sizes, int n_in,
                              void* d_out, int out_size) {
    const float* img1 = (const float*)d_in[0];
    const float* img2 = (const float*)d_in[1];
    float* out = (float*)d_out;

    cudaFuncSetAttribute(ssim_kernel,
                         cudaFuncAttributeMaxDynamicSharedMemorySize, SMEM_TOTAL);

    ssim_zero_kernel<<<1, 32>>>(out, out_size);

    dim3 block(256);
    dim3 grid((OUTD + TILE_W - 1) / TILE_W,   // 10
              (OUTD + TILE_H - 1) / TILE_H,   // 16
              NPLANE);                        // 48
    ssim_kernel<<<grid, block, SMEM_TOTAL>>>(img1, img2, out);
}

// round 17
// speedup vs baseline: 1.2905x; 1.2905x over previous
#include <cuda_runtime.h>

#define TILE_W  54          // output cols per block
#define TILE_H  32          // output rows per block
#define VCOLS   64          // input cols = TILE_W + 10
#define VSTR    65          // V row stride in float4 (odd -> conflict-free col access)
#define IMG     512
#define OUTD    502
#define NPLANE  48

#define V_BYTES    (TILE_H * VSTR * 16)     // 33280
#define SMEM_TOTAL (V_BYTES + 64)           // 33344 -> 6 CTAs/SM

__global__ void ssim_zero_kernel(float* out, int n) {
    int i = threadIdx.x;
    if (i < n) out[i] = 0.0f;
}

__global__ __launch_bounds__(256, 6) void ssim_kernel(const float* __restrict__ img1,
                                                      const float* __restrict__ img2,
                                                      float* __restrict__ out) {
    extern __shared__ char smem_raw[];
    float4 (*V)[VSTR] = (float4 (*)[VSTR])smem_raw;   // vertical 11-sums, 32 rows x 64 cols
    float* wsum = (float*)(smem_raw + V_BYTES);

    const int plane = blockIdx.z;
    const int batch = plane / 3;
    const int ox0 = blockIdx.x * TILE_W;
    const int oy0 = blockIdx.y * TILE_H;

    const float* __restrict__ p1 = img1 + (size_t)plane * IMG * IMG;
    const float* __restrict__ p2 = img2 + (size_t)plane * IMG * IMG;

    const int tid = threadIdx.x;

    // ---- Phase 1: vertical sliding 11-sums straight from GMEM (coalesced).
    //      256 threads: col c = tid&63, chunk = tid>>6 -> V rows chunk*8..chunk*8+7. ----
    {
        const int c  = tid & 63;
        const int r0 = (tid >> 6) * 8;

        // Block-uniform fast path: whole 42-row x 64-col input window in-bounds.
        if (oy0 + TILE_H + 10 <= IMG && ox0 + VCOLS <= IMG) {
            // All row addresses are base + k*IMG with compile-time k -> LDG [R, imm].
            const float* __restrict__ q1 = p1 + (size_t)(oy0 + r0) * IMG + (ox0 + c);
            const float* __restrict__ q2 = p2 + (size_t)(oy0 + r0) * IMG + (ox0 + c);

            // Exit rows 0..7 are prologue rows 0..7 -> keep (a,b) in registers.
            float ra[8], rb[8];
            float sa = 0.f, sb = 0.f, sp = 0.f, sm = 0.f;
            #pragma unroll
            for (int k = 0; k < 10; k++) {
                const float a = __saturatef(__ldg(q1 + k * IMG));
                const float b = __saturatef(__ldg(q2 + k * IMG));
                if (k < 8) { ra[k] = a; rb[k] = b; }
                const float pq = a + b, mq = a - b;
                sa += a; sb += b; sp += pq * pq; sm += mq * mq;
            }
            #pragma unroll
            for (int j = 0; j < 8; j++) {
                {   // enter row j+10 (the only load in the steady state)
                    const float a = __saturatef(__ldg(q1 + (j + 10) * IMG));
                    const float b = __saturatef(__ldg(q2 + (j + 10) * IMG));
                    const float pq = a + b, mq = a - b;
                    sa += a; sb += b; sp += pq * pq; sm += mq * mq;
                }
                V[r0 + j][c] = make_float4(sa, sb, sp, sm);
                {   // exit row j from registers
                    const float a = ra[j], b = rb[j];
                    const float pq = a + b, mq = a - b;
                    sa -= a; sb -= b; sp -= pq * pq; sm -= mq * mq;
                }
            }
        } else {
            // Boundary tiles: clamped coordinates (clamped lanes/rows only feed
            // guarded-out outputs).
            const int gx = min(ox0 + c, IMG - 1);
            const float* __restrict__ q1 = p1 + gx;
            const float* __restrict__ q2 = p2 + gx;

            float sa = 0.f, sb = 0.f, sp = 0.f, sm = 0.f;
            #pragma unroll
            for (int k = 0; k < 10; k++) {
                const int gy = min(oy0 + r0 + k, IMG - 1);
                const float a = __saturatef(__ldg(q1 + gy * IMG));
                const float b = __saturatef(__ldg(q2 + gy * IMG));
                const float pq = a + b, mq = a - b;
                sa += a; sb += b; sp += pq * pq; sm += mq * mq;
            }
            #pragma unroll
            for (int j = 0; j < 8; j++) {
                {
                    const int gy = min(oy0 + r0 + j + 10, IMG - 1);
                    const float a = __saturatef(__ldg(q1 + gy * IMG));
                    const float b = __saturatef(__ldg(q2 + gy * IMG));
                    const float pq = a + b, mq = a - b;
                    sa += a; sb += b; sp += pq * pq; sm += mq * mq;
                }
                V[r0 + j][c] = make_float4(sa, sb, sp, sm);
                {
                    const int gy = min(oy0 + r0 + j, IMG - 1);
                    const float a = __saturatef(__ldg(q1 + gy * IMG));
                    const float b = __saturatef(__ldg(q2 + gy * IMG));
                    const float pq = a + b, mq = a - b;
                    sa -= a; sb -= b; sp -= pq * pq; sm -= mq * mq;
                }
            }
        }
    }
    __syncthreads();

    // ---- Phase 2: horizontal sliding 11-sums of V + SSIM.
    //      256 threads: row = tid&31, span = tid>>5 (8 spans of 7 outputs). ----
    const float C1 = 1e-4f;
    const float C2 = 9e-4f;
    const float inv121 = 1.0f / 121.0f;
    const float inv242 = 1.0f / 242.0f;
    const float inv484 = 1.0f / 484.0f;

    float acc = 0.0f;
    {
        const int row = tid & 31;
        const int s0  = (tid >> 5) * 7;
        const bool rowok = (oy0 + row) < OUTD;

        float sa = 0.f, sb = 0.f, sp = 0.f, sm = 0.f;
        #pragma unroll
        for (int k = 0; k < 10; k++) {
            const float4 h = V[row][s0 + k];
            sa += h.x; sb += h.y; sp += h.z; sm += h.w;
        }
        #pragma unroll
        for (int j = 0; j < 7; j++) {
            if (s0 + j < TILE_W) {          // last span covers only 5 outputs
                {
                    const float4 h = V[row][s0 + j + 10];
                    sa += h.x; sb += h.y; sp += h.z; sm += h.w;
                }
                const int ox = ox0 + s0 + j;
                if (rowok && ox < OUTD) {
                    const float mu1  = sa * inv121;
                    const float mu2  = sb * inv121;
                    const float musq = mu1 * mu1 + mu2 * mu2;
                    const float mu12 = mu1 * mu2;
                    const float e_sq = (sp + sm) * inv242;   // E[a^2 + b^2]
                    const float e_ab = (sp - sm) * inv484;   // E[ab]
                    const float vsum = e_sq - musq;          // v1 + v2
                    const float v12  = e_ab - mu12;
                    const float num = (2.0f * mu12 + C1) * (2.0f * v12 + C2);
                    const float den = (musq + C1) * (vsum + C2);
                    acc += __fdividef(num, den);
                }
                {
                    const float4 h = V[row][s0 + j];
                    sa -= h.x; sb -= h.y; sp -= h.z; sm -= h.w;
                }
            }
        }
    }

    // ---- Block reduction ----
    #pragma unroll
    for (int o = 16; o > 0; o >>= 1)
        acc += __shfl_down_sync(0xffffffffu, acc, o);
    if ((tid & 31) == 0) wsum[tid >> 5] = acc;
    __syncthreads();
    if (tid == 0) {
        float t = 0.0f;
        #pragma unroll
        for (int i = 0; i < 8; i++) t += wsum[i];
        const float scale = 1.0f / (3.0f * (float)OUTD * (float)OUTD);
        atomicAdd(out + batch, t * scale);
    }
}

extern "C" void kernel_launch(void* const* d_in, const int* in_sizes, int n_in,
                              void* d_out, int out_size) {
    const float* img1 = (const float*)d_in[0];
    const float* img2 = (const float*)d_in[1];
    float* out = (float*)d_out;

    cudaFuncSetAttribute(ssim_kernel,
                         cudaFuncAttributeMaxDynamicSharedMemorySize, SMEM_TOTAL);

    ssim_zero_kernel<<<1, 32>>>(out, out_size);

    dim3 block(256);
    dim3 grid((OUTD + TILE_W - 1) / TILE_W,   // 10
              (OUTD + TILE_H - 1) / TILE_H,   // 16
              NPLANE);                        // 48
    ssim_kernel<<<grid, block, SMEM_TOTAL>>>(img1, img2, out);
}